// round 1
// baseline (speedup 1.0000x reference)
#include <cuda_runtime.h>

// mysoftmax: per-pixel softmax over C=19 + variance propagation through
// squared softmax Jacobian.
//   p = softmax(mu)                              [B*N, C]
//   sigma_out_i = sum_j (p_i(d_ij - p_j))^2 * sigma_j
//               = p_i^2 * ( S + (1 - 2 p_i) * sigma_i ),  S = sum_j p_j^2 sigma_j
//
// d_out layout: [p (B*N*C floats), sigma_out (B*N*C floats)]

static constexpr int C = 19;
static constexpr int PIX_PER_BLK = 256;
static constexpr int TILE = PIX_PER_BLK * C;   // 4864 floats, divisible by 4
static constexpr int TILE4 = TILE / 4;         // 1216 float4

__global__ __launch_bounds__(PIX_PER_BLK)
void mysoftmax_kernel(const float* __restrict__ mu,
                      const float* __restrict__ sg,
                      float* __restrict__ out,
                      long long total_elems)   // B*N*C
{
    __shared__ float smu[TILE];
    __shared__ float ssg[TILE];

    const int t = threadIdx.x;
    const long long base = (long long)blockIdx.x * TILE;

    // ---- coalesced vectorized load: gmem -> smem ----
    const float4* __restrict__ mu4 = reinterpret_cast<const float4*>(mu + base);
    const float4* __restrict__ sg4 = reinterpret_cast<const float4*>(sg + base);
    float4* smu4 = reinterpret_cast<float4*>(smu);
    float4* ssg4 = reinterpret_cast<float4*>(ssg);

    #pragma unroll
    for (int i = 0; i < (TILE4 + PIX_PER_BLK - 1) / PIX_PER_BLK; i++) {
        int idx = t + i * PIX_PER_BLK;
        if (idx < TILE4) {
            smu4[idx] = mu4[idx];
            ssg4[idx] = sg4[idx];
        }
    }
    __syncthreads();

    // ---- per-pixel compute (one pixel per thread) ----
    // smem row stride 19 (odd) -> bank-conflict-free across the warp.
    float v[C];
    float sv[C];

    float m = -3.402823466e+38f;
    #pragma unroll
    for (int j = 0; j < C; j++) {
        v[j] = smu[t * C + j];
        m = fmaxf(m, v[j]);
    }

    float sum = 0.0f;
    #pragma unroll
    for (int j = 0; j < C; j++) {
        v[j] = __expf(v[j] - m);
        sum += v[j];
    }
    const float inv = __frcp_rn(sum);

    float S = 0.0f;
    #pragma unroll
    for (int j = 0; j < C; j++) {
        v[j] *= inv;                 // p_j
        sv[j] = ssg[t * C + j];      // sigma_j
        S = fmaf(v[j] * v[j], sv[j], S);
    }

    __syncthreads();   // done reading smem before overwrite

    #pragma unroll
    for (int j = 0; j < C; j++) {
        const float p = v[j];
        smu[t * C + j] = p;
        ssg[t * C + j] = p * p * (S + (1.0f - 2.0f * p) * sv[j]);
    }
    __syncthreads();

    // ---- coalesced vectorized store: smem -> gmem ----
    float4* __restrict__ outp = reinterpret_cast<float4*>(out + base);
    float4* __restrict__ outs = reinterpret_cast<float4*>(out + total_elems + base);

    #pragma unroll
    for (int i = 0; i < (TILE4 + PIX_PER_BLK - 1) / PIX_PER_BLK; i++) {
        int idx = t + i * PIX_PER_BLK;
        if (idx < TILE4) {
            outp[idx] = smu4[idx];
            outs[idx] = ssg4[idx];
        }
    }
}

extern "C" void kernel_launch(void* const* d_in, const int* in_sizes, int n_in,
                              void* d_out, int out_size)
{
    const float* mu = (const float*)d_in[0];
    const float* sg = (const float*)d_in[1];
    float* out = (float*)d_out;

    const long long total_elems = (long long)in_sizes[0];        // B*N*C = 4,980,736
    const int n_pix = (int)(total_elems / C);                    // 262,144
    const int n_blocks = n_pix / PIX_PER_BLK;                    // 1024

    mysoftmax_kernel<<<n_blocks, PIX_PER_BLK>>>(mu, sg, out, total_elems);
}

// round 2
// speedup vs baseline: 1.1327x; 1.1327x over previous
#include <cuda_runtime.h>

// mysoftmax: per-pixel softmax over C=19 + variance propagation through
// squared softmax Jacobian.
//   p = softmax(mu)
//   sigma_out_i = p_i^2 * ( S + (1 - 2 p_i) * sigma_i ),  S = sum_j p_j^2 sigma_j
//
// d_out layout: [p (B*N*C floats), sigma_out (B*N*C floats)]
//
// R1 changes: 128-thread blocks (2048 blocks, smaller wave tail), dropped the
// sv[19] register array (re-read sigma from smem; row-private so no extra
// sync), dropped the mid-kernel __syncthreads. Target: occupancy-bound ->
// DRAM-bound.

static constexpr int C = 19;
static constexpr int PIX_PER_BLK = 128;
static constexpr int TILE = PIX_PER_BLK * C;   // 2432 floats, divisible by 4
static constexpr int TILE4 = TILE / 4;         // 608 float4
static constexpr int NITER = (TILE4 + PIX_PER_BLK - 1) / PIX_PER_BLK;  // 5

__global__ __launch_bounds__(PIX_PER_BLK)
void mysoftmax_kernel(const float* __restrict__ mu,
                      const float* __restrict__ sg,
                      float* __restrict__ out,
                      long long total_elems)   // B*N*C
{
    __shared__ float smu[TILE];
    __shared__ float ssg[TILE];

    const int t = threadIdx.x;
    const long long base = (long long)blockIdx.x * TILE;

    // ---- coalesced vectorized load: gmem -> smem ----
    const float4* __restrict__ mu4 = reinterpret_cast<const float4*>(mu + base);
    const float4* __restrict__ sg4 = reinterpret_cast<const float4*>(sg + base);
    float4* smu4 = reinterpret_cast<float4*>(smu);
    float4* ssg4 = reinterpret_cast<float4*>(ssg);

    #pragma unroll
    for (int i = 0; i < NITER; i++) {
        int idx = t + i * PIX_PER_BLK;
        if (idx < TILE4) {
            smu4[idx] = mu4[idx];
            ssg4[idx] = sg4[idx];
        }
    }
    __syncthreads();

    // ---- per-pixel compute (one pixel per thread) ----
    // smem row stride 19 (odd) -> bank-conflict-free across the warp.
    // Each thread only reads/writes its OWN row between the two syncs, so no
    // intermediate __syncthreads is needed.
    float v[C];

    float m = -3.402823466e+38f;
    #pragma unroll
    for (int j = 0; j < C; j++) {
        v[j] = smu[t * C + j];
        m = fmaxf(m, v[j]);
    }

    float sum = 0.0f;
    #pragma unroll
    for (int j = 0; j < C; j++) {
        v[j] = __expf(v[j] - m);
        sum += v[j];
    }
    const float inv = __frcp_rn(sum);

    float S = 0.0f;
    #pragma unroll
    for (int j = 0; j < C; j++) {
        v[j] *= inv;                            // p_j
        S = fmaf(v[j] * v[j], ssg[t * C + j], S);
    }

    #pragma unroll
    for (int j = 0; j < C; j++) {
        const float p  = v[j];
        const float sg_j = ssg[t * C + j];      // read own row, then overwrite
        smu[t * C + j] = p;
        ssg[t * C + j] = p * p * (S + (1.0f - 2.0f * p) * sg_j);
    }
    __syncthreads();

    // ---- coalesced vectorized store: smem -> gmem ----
    float4* __restrict__ outp = reinterpret_cast<float4*>(out + base);
    float4* __restrict__ outs = reinterpret_cast<float4*>(out + total_elems + base);

    #pragma unroll
    for (int i = 0; i < NITER; i++) {
        int idx = t + i * PIX_PER_BLK;
        if (idx < TILE4) {
            outp[idx] = smu4[idx];
            outs[idx] = ssg4[idx];
        }
    }
}

extern "C" void kernel_launch(void* const* d_in, const int* in_sizes, int n_in,
                              void* d_out, int out_size)
{
    const float* mu = (const float*)d_in[0];
    const float* sg = (const float*)d_in[1];
    float* out = (float*)d_out;

    const long long total_elems = (long long)in_sizes[0];        // B*N*C = 4,980,736
    const int n_pix = (int)(total_elems / C);                    // 262,144
    const int n_blocks = n_pix / PIX_PER_BLK;                    // 2048

    mysoftmax_kernel<<<n_blocks, PIX_PER_BLK>>>(mu, sg, out, total_elems);
}

// round 3
// speedup vs baseline: 1.1378x; 1.0044x over previous
#include <cuda_runtime.h>
#include <cstdint>

// mysoftmax: per-pixel softmax over C=19 + variance propagation through the
// squared softmax Jacobian.
//   p = softmax(mu)
//   sigma_out_i = p_i^2 * ( S + (1 - 2 p_i) * sigma_i ),  S = sum_j p_j^2 sigma_j
//
// d_out layout: [p (B*N*C floats), sigma_out (B*N*C floats)]
//
// R2: persistent grid (148*5 = 740 blocks), double-buffered cp.async pipeline.
// While computing tile i out of smem buffer A, tile i+1 is prefetched into
// buffer B. Removes wave quantization and hides load latency inside the block.

static constexpr int C = 19;
static constexpr int PIX_PER_BLK = 128;
static constexpr int TILE = PIX_PER_BLK * C;   // 2432 floats
static constexpr int TILE4 = TILE / 4;         // 608 float4 (not divisible by 128)
static constexpr int NITER = (TILE4 + PIX_PER_BLK - 1) / PIX_PER_BLK;  // 5
static constexpr int NSTAGE = 2;

__device__ __forceinline__ uint32_t smem_u32(const void* p) {
    return (uint32_t)__cvta_generic_to_shared(p);
}

__device__ __forceinline__ void cp_async16(uint32_t dst, const void* src) {
    asm volatile("cp.async.cg.shared.global [%0], [%1], 16;\n"
                 :: "r"(dst), "l"(src));
}

__device__ __forceinline__ void cp_commit() {
    asm volatile("cp.async.commit_group;\n" ::: "memory");
}

template <int N>
__device__ __forceinline__ void cp_wait() {
    asm volatile("cp.async.wait_group %0;\n" :: "n"(N) : "memory");
}

__global__ __launch_bounds__(PIX_PER_BLK)
void mysoftmax_kernel(const float* __restrict__ mu,
                      const float* __restrict__ sg,
                      float* __restrict__ out,
                      long long total_elems,   // B*N*C
                      int ntiles)
{
    __shared__ __align__(16) float smu[NSTAGE][TILE];
    __shared__ __align__(16) float ssg[NSTAGE][TILE];

    const int t = threadIdx.x;
    const int stride = gridDim.x;

    // ---- issue loads for a tile into stage s ----
    auto issue_tile = [&](int tile, int s) {
        const long long base = (long long)tile * TILE;
        const float4* mu4 = reinterpret_cast<const float4*>(mu + base);
        const float4* sg4 = reinterpret_cast<const float4*>(sg + base);
        uint32_t dmu = smem_u32(&smu[s][0]);
        uint32_t dsg = smem_u32(&ssg[s][0]);
        #pragma unroll
        for (int i = 0; i < NITER; i++) {
            int idx = t + i * PIX_PER_BLK;
            if (idx < TILE4) {
                cp_async16(dmu + idx * 16, mu4 + idx);
                cp_async16(dsg + idx * 16, sg4 + idx);
            }
        }
        cp_commit();
    };

    int tile = blockIdx.x;
    if (tile >= ntiles) return;

    // prologue: prefetch first tile
    issue_tile(tile, 0);

    int buf = 0;
    for (; tile < ntiles; tile += stride) {
        const int next = tile + stride;
        const bool has_next = (next < ntiles);

        // overlap: prefetch next tile into the other buffer.
        // (previous iteration's trailing __syncthreads guarantees buf^1 free)
        if (has_next) issue_tile(next, buf ^ 1);

        // wait for current tile's data (allow the just-issued group in flight)
        if (has_next) cp_wait<1>(); else cp_wait<0>();
        __syncthreads();

        float* __restrict__ cmu = smu[buf];
        float* __restrict__ csg = ssg[buf];

        // ---- per-pixel compute (one pixel per thread) ----
        // smem row stride 19 (odd) -> conflict-free across the warp.
        float v[C];

        float m = -3.402823466e+38f;
        #pragma unroll
        for (int j = 0; j < C; j++) {
            v[j] = cmu[t * C + j];
            m = fmaxf(m, v[j]);
        }

        float sum = 0.0f;
        #pragma unroll
        for (int j = 0; j < C; j++) {
            v[j] = __expf(v[j] - m);
            sum += v[j];
        }
        const float inv = __frcp_rn(sum);

        float S = 0.0f;
        #pragma unroll
        for (int j = 0; j < C; j++) {
            v[j] *= inv;                            // p_j
            S = fmaf(v[j] * v[j], csg[t * C + j], S);
        }

        #pragma unroll
        for (int j = 0; j < C; j++) {
            const float p    = v[j];
            const float sg_j = csg[t * C + j];      // own row: read then overwrite
            cmu[t * C + j] = p;
            csg[t * C + j] = p * p * (S + (1.0f - 2.0f * p) * sg_j);
        }
        __syncthreads();

        // ---- coalesced vectorized store: smem -> gmem ----
        const long long base = (long long)tile * TILE;
        float4* __restrict__ outp = reinterpret_cast<float4*>(out + base);
        float4* __restrict__ outs = reinterpret_cast<float4*>(out + total_elems + base);
        const float4* cmu4 = reinterpret_cast<const float4*>(cmu);
        const float4* csg4 = reinterpret_cast<const float4*>(csg);

        #pragma unroll
        for (int i = 0; i < NITER; i++) {
            int idx = t + i * PIX_PER_BLK;
            if (idx < TILE4) {
                outp[idx] = cmu4[idx];
                outs[idx] = csg4[idx];
            }
        }
        __syncthreads();   // all threads done with buf before it is refilled

        buf ^= 1;
    }
}

extern "C" void kernel_launch(void* const* d_in, const int* in_sizes, int n_in,
                              void* d_out, int out_size)
{
    const float* mu = (const float*)d_in[0];
    const float* sg = (const float*)d_in[1];
    float* out = (float*)d_out;

    const long long total_elems = (long long)in_sizes[0];        // B*N*C = 4,980,736
    const int n_pix = (int)(total_elems / C);                    // 262,144
    const int ntiles = n_pix / PIX_PER_BLK;                      // 2048

    // persistent-style grid: 5 blocks/SM (smem-limited) * 148 SMs
    int grid = 148 * 5;
    if (grid > ntiles) grid = ntiles;

    mysoftmax_kernel<<<grid, PIX_PER_BLK>>>(mu, sg, out, total_elems, ntiles);
}